// round 11
// baseline (speedup 1.0000x reference)
#include <cuda_runtime.h>
#include <cuda_fp16.h>
#include <cstdint>

// ---------------------------------------------------------------------------
// y[m, o] = (sum_k x[m,k] * w_q[o,k]) * 2^s_exp[o] + bias[o]
// M = 16384, N = 2048, K = 2048.
// Launch 1: fused prep(scale/bias) + x fp32->fp16 + w->fp16 (MLP=4).
// Launch 2: HMMA GEMM (BM=128, BN=256, BK=64, 3-stage) with REGISTER
//           DOUBLE-BUFFERED fragments: ks+1 LDSMs issue before ks MMAs so the
//           ldsm->mma scoreboard stall leaves the critical path.
//           (R10 ncu: tensor 67.5%, DRAM 6% -> tensor-util-bound.)
// ---------------------------------------------------------------------------

static constexpr int M_TOTAL = 16384;
static constexpr int N_TOTAL = 2048;
static constexpr int K_TOTAL = 2048;

static constexpr int BM = 128;
static constexpr int BN = 256;
static constexpr int BK = 64;                 // 64 halves = 128 B per row
static constexpr int KITERS = K_TOTAL / BK;   // 32
static constexpr int STAGES = 3;
static constexpr int THREADS = 512;           // 16 warps: 4 (m) x 4 (n)

static constexpr uint32_t A_STAGE_BYTES = BM * 128;           // 16384
static constexpr uint32_t B_STAGE_BYTES = BN * 128;           // 32768
static constexpr uint32_t STAGE_BYTES   = A_STAGE_BYTES + B_STAGE_BYTES; // 49152
static constexpr uint32_t SMEM_TOTAL    = STAGES * STAGE_BYTES;          // 147456

// scratch
__device__ __half g_x16[(size_t)M_TOTAL * K_TOTAL];   // 64 MB
__device__ __half g_w16[(size_t)N_TOTAL * K_TOTAL];   // 8 MB
__device__ float  g_scale[N_TOTAL];
__device__ float  g_bias[N_TOTAL];

// ---------------------------------------------------------------------------
// helpers
// ---------------------------------------------------------------------------
__device__ __forceinline__ uint32_t smem_to_u32(const void* p) {
    uint32_t a;
    asm("{ .reg .u64 t; cvta.to.shared.u64 t, %1; cvt.u32.u64 %0, t; }"
        : "=r"(a) : "l"(p));
    return a;
}

__device__ __forceinline__ void cp_async_16(uint32_t saddr, const void* gptr) {
    asm volatile("cp.async.cg.shared.global [%0], [%1], 16;"
                 :: "r"(saddr), "l"(gptr) : "memory");
}
__device__ __forceinline__ void cp_async_commit() {
    asm volatile("cp.async.commit_group;" ::: "memory");
}
template <int N>
__device__ __forceinline__ void cp_async_wait() {
    asm volatile("cp.async.wait_group %0;" :: "n"(N) : "memory");
}

__device__ __forceinline__ void ldsm_x4(uint32_t& r0, uint32_t& r1,
                                        uint32_t& r2, uint32_t& r3, uint32_t addr) {
    asm volatile("ldmatrix.sync.aligned.m8n8.x4.shared.b16 {%0,%1,%2,%3}, [%4];"
                 : "=r"(r0), "=r"(r1), "=r"(r2), "=r"(r3) : "r"(addr));
}

__device__ __forceinline__ void mma_16816(float* c, const uint32_t* a, const uint32_t* b) {
    asm volatile(
        "mma.sync.aligned.m16n8k16.row.col.f32.f16.f16.f32 "
        "{%0,%1,%2,%3}, {%4,%5,%6,%7}, {%8,%9}, {%0,%1,%2,%3};"
        : "+f"(c[0]), "+f"(c[1]), "+f"(c[2]), "+f"(c[3])
        : "r"(a[0]), "r"(a[1]), "r"(a[2]), "r"(a[3]), "r"(b[0]), "r"(b[1]));
}

// per-128B-row XOR swizzle: physical 16B-chunk = chunk ^ (row & 7)
__device__ __forceinline__ uint32_t sw_off(int row, int chunk) {
    return (uint32_t)(row * 128 + ((chunk ^ (row & 7)) << 4));
}

// ---------------------------------------------------------------------------
// dtype / binding detection
// ---------------------------------------------------------------------------
__device__ __forceinline__ int looks_se_bytes(const unsigned char* p) {
    int ok = 1;
#pragma unroll 8
    for (int i = 0; i < 64; ++i) {
        unsigned char b = p[i];
        if (!(b == 0x00 || b >= 0xF8)) ok = 0;
    }
    return ok;
}
__device__ __forceinline__ int looks_i32_groups(const unsigned char* p, int groups,
                                                unsigned char lo_min) {
    int ok = 1;
#pragma unroll 4
    for (int j = 0; j < groups; ++j) {
        unsigned char b0 = p[4 * j], b1 = p[4 * j + 1],
                      b2 = p[4 * j + 2], b3 = p[4 * j + 3];
        unsigned char ext = (b0 >= lo_min) ? 0xFF : 0x00;
        int b0ok = (b0 == 0x00) || (b0 == 0x01 && lo_min == 0xFF) || (b0 >= lo_min);
        if (!(b0ok && b1 == ext && b2 == ext && b3 == ext)) ok = 0;
    }
    return ok;
}

// ---------------------------------------------------------------------------
// Launch 1: fused prep + converts (identical to the R10 377.7us version)
// ---------------------------------------------------------------------------
static constexpr int XBLK = M_TOTAL * K_TOTAL / 8192;   // 4096
static constexpr int WBLK = N_TOTAL * K_TOTAL / 4096;   // 1024

__global__ void __launch_bounds__(256)
prep_cvt_kernel(const float* __restrict__ x, const void* __restrict__ wq,
                const void* __restrict__ c0, const void* __restrict__ c1) {
    const int b = blockIdx.x;
    const int tid = threadIdx.x;
    if (b == 0) {
        const int c0_is_se = looks_se_bytes((const unsigned char*)c0);
        const void*  sep = c0_is_se ? c0 : c1;
        const float* bi  = (const float*)(c0_is_se ? c1 : c0);
        const int se32 = looks_i32_groups((const unsigned char*)sep, 64, 0xF8);
#pragma unroll
        for (int t = 0; t < 8; ++t) {
            const int i = tid + t * 256;
            const int e = se32 ? ((const int*)sep)[i]
                               : (int)((const signed char*)sep)[i];
            g_scale[i] = __int_as_float((127 + e) << 23);   // exact 2^s_exp
            g_bias[i]  = bi[i];
        }
    } else if (b <= XBLK) {
        const size_t slot0 = (size_t)(b - 1) * 2048;
        const float4* xi = reinterpret_cast<const float4*>(x) + slot0;
        uint2*        xo = reinterpret_cast<uint2*>(g_x16) + slot0;
#pragma unroll
        for (int batch = 0; batch < 2; ++batch) {
            float4 v[4];
#pragma unroll
            for (int t = 0; t < 4; ++t)
                v[t] = __ldcs(xi + tid + (batch * 4 + t) * 256);
#pragma unroll
            for (int t = 0; t < 4; ++t) {
                __half2 a = __floats2half2_rn(v[t].x, v[t].y);
                __half2 c = __floats2half2_rn(v[t].z, v[t].w);
                uint2 o;
                o.x = *reinterpret_cast<const uint32_t*>(&a);
                o.y = *reinterpret_cast<const uint32_t*>(&c);
                xo[tid + (batch * 4 + t) * 256] = o;
            }
        }
    } else {
        const int w_is32 = looks_i32_groups((const unsigned char*)wq, 64, 0xFF);
        const size_t e0 = (size_t)(b - 1 - XBLK) * 4096;
        if (w_is32) {
            const int4* wi = reinterpret_cast<const int4*>((const int*)wq + e0);
            int4 v[4];
#pragma unroll
            for (int t = 0; t < 4; ++t)
                v[t] = __ldcs(wi + tid + t * 256);
#pragma unroll
            for (int t = 0; t < 4; ++t) {
                const int slot = tid + t * 256;
                uint32_t u0 = (((uint32_t)v[t].x >> 16) & 0x8000u)
                            | ((uint32_t)(v[t].x & 1) * 0x3C00u);
                uint32_t u1 = (((uint32_t)v[t].y >> 16) & 0x8000u)
                            | ((uint32_t)(v[t].y & 1) * 0x3C00u);
                uint32_t u2 = (((uint32_t)v[t].z >> 16) & 0x8000u)
                            | ((uint32_t)(v[t].z & 1) * 0x3C00u);
                uint32_t u3 = (((uint32_t)v[t].w >> 16) & 0x8000u)
                            | ((uint32_t)(v[t].w & 1) * 0x3C00u);
                uint2 o; o.x = u0 | (u1 << 16); o.y = u2 | (u3 << 16);
                reinterpret_cast<uint2*>(g_w16 + e0)[slot] = o;
            }
        } else {
#pragma unroll
            for (int t = 0; t < 2; ++t) {
                const int slot = tid + t * 256;
                unsigned long long v = reinterpret_cast<const unsigned long long*>(
                    (const signed char*)wq + e0)[slot];
                uint32_t h2[4];
#pragma unroll
                for (int j = 0; j < 4; ++j) {
                    int b0 = (int)(signed char)(v >> (16 * j));
                    int b1 = (int)(signed char)(v >> (16 * j + 8));
                    uint32_t u0 = ((uint32_t)(b0 << 8) & 0x8000u) | ((uint32_t)(b0 & 1) * 0x3C00u);
                    uint32_t u1 = ((uint32_t)(b1 << 8) & 0x8000u) | ((uint32_t)(b1 & 1) * 0x3C00u);
                    h2[j] = u0 | (u1 << 16);
                }
                uint4 q; q.x = h2[0]; q.y = h2[1]; q.z = h2[2]; q.w = h2[3];
                reinterpret_cast<uint4*>(g_w16 + e0)[slot] = q;
            }
        }
    }
}

// ---------------------------------------------------------------------------
// Launch 2: GEMM with register double-buffered fragments.
// grid = (N/BN=8, M/BM=128), 512 threads, warp (wm, wn) in 4x4, tile 32x64.
// ---------------------------------------------------------------------------
__global__ void __launch_bounds__(THREADS, 1)
bitlinear_gemm_kernel(float* __restrict__ out) {
    extern __shared__ __align__(1024) char smem[];
    const uint32_t smem_base = smem_to_u32(smem);

    const int tid  = threadIdx.x;
    const int warp = tid >> 5;
    const int lane = tid & 31;
    const int wm   = warp >> 2;      // 0..3
    const int wn   = warp & 3;       // 0..3

    const int n0 = blockIdx.x * BN;
    const int m0 = blockIdx.y * BM;

    const __half* gA = g_x16 + (size_t)m0 * K_TOTAL;
    const __half* gW = g_w16 + (size_t)n0 * K_TOTAL;

    auto issue_stage = [&](int c, int s) {
        const uint32_t sa = smem_base + (uint32_t)s * STAGE_BYTES;
        const uint32_t sb = sa + A_STAGE_BYTES;
        const int kb = c * BK;
#pragma unroll
        for (int t = 0; t < 2; ++t) {                 // A: 1024 chunks
            int idx = tid + t * THREADS;
            int r = idx >> 3, ch = idx & 7;
            cp_async_16(sa + sw_off(r, ch), gA + (size_t)r * K_TOTAL + kb + ch * 8);
        }
#pragma unroll
        for (int t = 0; t < 4; ++t) {                 // B: 2048 chunks
            int idx = tid + t * THREADS;
            int r = idx >> 3, ch = idx & 7;
            cp_async_16(sb + sw_off(r, ch), gW + (size_t)r * K_TOTAL + kb + ch * 8);
        }
    };

    issue_stage(0, 0); cp_async_commit();
    issue_stage(1, 1); cp_async_commit();

    float acc[2][8][4];
#pragma unroll
    for (int i = 0; i < 2; ++i)
#pragma unroll
        for (int j = 0; j < 8; ++j)
#pragma unroll
            for (int k = 0; k < 4; ++k) acc[i][j][k] = 0.f;

    const int a_row_in = (lane & 7) + ((lane >> 3) & 1) * 8;
    const int a_chpar  = lane >> 4;
    const int b_row_in = ((lane >> 4) << 3) + (lane & 7);
    const int b_chpar  = (lane >> 3) & 1;

    // fixed swizzled base offsets for this thread's ldsm rows
    const uint32_t a_off0 = sw_off(wm * 32 +  0 + a_row_in, 0);
    const uint32_t a_off1 = sw_off(wm * 32 + 16 + a_row_in, 0);
    // note: sw_off(row, ch) = sw_off(row, 0) ^ (((ch ^ 0) relative)) — chunk
    // dependence must be recomputed since XOR depends on row; keep full calls.

    float2 sc01[8], bi01[8];   // preloaded epilogue constants? (kept in loop below)

    uint32_t af[2][2][4];      // [buf][mtile][regs]
    uint32_t bf[2][8][2];      // [buf][ntile][regs]

#pragma unroll 1
    for (int c = 0; c < KITERS; ++c) {
        cp_async_wait<1>();
        __syncthreads();
        if (c + 2 < KITERS) issue_stage(c + 2, (c + 2) % STAGES);
        cp_async_commit();

        const int s = c % STAGES;
        const uint32_t sa = smem_base + (uint32_t)s * STAGE_BYTES;
        const uint32_t sb = sa + A_STAGE_BYTES;

        auto load_frags = [&](int ks, int buf) {
#pragma unroll
            for (int i = 0; i < 2; ++i) {
                int m = wm * 32 + i * 16 + a_row_in;
                ldsm_x4(af[buf][i][0], af[buf][i][1], af[buf][i][2], af[buf][i][3],
                        sa + sw_off(m, ks * 2 + a_chpar));
            }
#pragma unroll
            for (int p = 0; p < 4; ++p) {
                int n = wn * 64 + p * 16 + b_row_in;
                uint32_t r0, r1, r2, r3;
                ldsm_x4(r0, r1, r2, r3, sb + sw_off(n, ks * 2 + b_chpar));
                bf[buf][2 * p][0] = r0;     bf[buf][2 * p][1] = r1;
                bf[buf][2 * p + 1][0] = r2; bf[buf][2 * p + 1][1] = r3;
            }
        };

        load_frags(0, 0);                      // prime ks=0
#pragma unroll
        for (int ks = 0; ks < 4; ++ks) {
            const int cur = ks & 1;
            if (ks < 3) load_frags(ks + 1, cur ^ 1);   // prefetch before MMAs
#pragma unroll
            for (int i = 0; i < 2; ++i)
#pragma unroll
                for (int j = 0; j < 8; ++j)
                    mma_16816(acc[i][j], af[cur][i], bf[cur][j]);
        }
    }

    // epilogue: y * 2^s_exp + bias; streaming stores
    const int col_lo = 2 * (lane & 3);
    const int row_lo = lane >> 2;
#pragma unroll
    for (int j = 0; j < 8; ++j) {
        const int nc = n0 + wn * 64 + j * 8 + col_lo;
        const float s0 = g_scale[nc], s1 = g_scale[nc + 1];
        const float b0 = g_bias[nc],  b1 = g_bias[nc + 1];
#pragma unroll
        for (int i = 0; i < 2; ++i) {
            const int mr = m0 + wm * 32 + i * 16 + row_lo;
            float2 v0, v1;
            v0.x = acc[i][j][0] * s0 + b0;  v0.y = acc[i][j][1] * s1 + b1;
            v1.x = acc[i][j][2] * s0 + b0;  v1.y = acc[i][j][3] * s1 + b1;
            __stcs(reinterpret_cast<float2*>(out + (size_t)mr * N_TOTAL + nc), v0);
            __stcs(reinterpret_cast<float2*>(out + (size_t)(mr + 8) * N_TOTAL + nc), v1);
        }
    }
}

// ---------------------------------------------------------------------------
// host launcher — bind by element count; 2 launches per call
// ---------------------------------------------------------------------------
extern "C" void kernel_launch(void* const* d_in, const int* in_sizes, int n_in,
                              void* d_out, int out_size) {
    const void* x_p  = nullptr;
    const void* w_p  = nullptr;
    const void* c0_p = nullptr;
    const void* c1_p = nullptr;
    for (int i = 0; i < n_in; ++i) {
        if      (in_sizes[i] == M_TOTAL * K_TOTAL) x_p = d_in[i];
        else if (in_sizes[i] == N_TOTAL * K_TOTAL) w_p = d_in[i];
        else if (!c0_p)                            c0_p = d_in[i];
        else                                       c1_p = d_in[i];
    }
    float* out = (float*)d_out;

    static bool attr_set = false;
    if (!attr_set) {
        cudaFuncSetAttribute(bitlinear_gemm_kernel,
                             cudaFuncAttributeMaxDynamicSharedMemorySize, SMEM_TOTAL);
        attr_set = true;
    }

    prep_cvt_kernel<<<1 + XBLK + WBLK, 256>>>((const float*)x_p, w_p, c0_p, c1_p);

    dim3 grid(N_TOTAL / BN, M_TOTAL / BM);   // (8, 128), n fastest
    bitlinear_gemm_kernel<<<grid, THREADS, SMEM_TOTAL>>>(out);
}

// round 12
// speedup vs baseline: 1.0532x; 1.0532x over previous
#include <cuda_runtime.h>
#include <cuda_fp16.h>
#include <cstdint>

// ---------------------------------------------------------------------------
// y[m, o] = (sum_k x[m,k] * w_q[o,k]) * 2^s_exp[o] + bias[o]
// M = 16384, N = 2048, K = 2048.
// Launch 1: fused prep(scale/bias) + x fp32->fp16 + w->fp16 (MLP=4).
// Launch 2: HMMA GEMM, BM=128 BN=256 BK=64, FOUR stages, TWO chunks per sync
//           round (16 rounds vs 32) — attacks the chunk-boundary bar/wait idle
//           that keeps tensor at 67% (R10/R11 ncu; memory pipes all <16%).
//           Inner loop is the R10 single-buffered body (R11 showed no register
//           headroom for fragment double-buffering at 128 regs/thread).
// ---------------------------------------------------------------------------

static constexpr int M_TOTAL = 16384;
static constexpr int N_TOTAL = 2048;
static constexpr int K_TOTAL = 2048;

static constexpr int BM = 128;
static constexpr int BN = 256;
static constexpr int BK = 64;                 // 64 halves = 128 B per row
static constexpr int KITERS = K_TOTAL / BK;   // 32 chunks, 16 rounds
static constexpr int STAGES = 4;
static constexpr int THREADS = 512;           // 16 warps: 4 (m) x 4 (n)

static constexpr uint32_t A_STAGE_BYTES = BM * 128;           // 16384
static constexpr uint32_t B_STAGE_BYTES = BN * 128;           // 32768
static constexpr uint32_t STAGE_BYTES   = A_STAGE_BYTES + B_STAGE_BYTES; // 49152
static constexpr uint32_t SMEM_TOTAL    = STAGES * STAGE_BYTES;          // 196608

// scratch
__device__ __half g_x16[(size_t)M_TOTAL * K_TOTAL];   // 64 MB
__device__ __half g_w16[(size_t)N_TOTAL * K_TOTAL];   // 8 MB
__device__ float  g_scale[N_TOTAL];
__device__ float  g_bias[N_TOTAL];

// ---------------------------------------------------------------------------
// helpers
// ---------------------------------------------------------------------------
__device__ __forceinline__ uint32_t smem_to_u32(const void* p) {
    uint32_t a;
    asm("{ .reg .u64 t; cvta.to.shared.u64 t, %1; cvt.u32.u64 %0, t; }"
        : "=r"(a) : "l"(p));
    return a;
}

__device__ __forceinline__ void cp_async_16(uint32_t saddr, const void* gptr) {
    asm volatile("cp.async.cg.shared.global [%0], [%1], 16;"
                 :: "r"(saddr), "l"(gptr) : "memory");
}
__device__ __forceinline__ void cp_async_commit() {
    asm volatile("cp.async.commit_group;" ::: "memory");
}
template <int N>
__device__ __forceinline__ void cp_async_wait() {
    asm volatile("cp.async.wait_group %0;" :: "n"(N) : "memory");
}

__device__ __forceinline__ void ldsm_x4(uint32_t& r0, uint32_t& r1,
                                        uint32_t& r2, uint32_t& r3, uint32_t addr) {
    asm volatile("ldmatrix.sync.aligned.m8n8.x4.shared.b16 {%0,%1,%2,%3}, [%4];"
                 : "=r"(r0), "=r"(r1), "=r"(r2), "=r"(r3) : "r"(addr));
}

__device__ __forceinline__ void mma_16816(float* c, const uint32_t* a, const uint32_t* b) {
    asm volatile(
        "mma.sync.aligned.m16n8k16.row.col.f32.f16.f16.f32 "
        "{%0,%1,%2,%3}, {%4,%5,%6,%7}, {%8,%9}, {%0,%1,%2,%3};"
        : "+f"(c[0]), "+f"(c[1]), "+f"(c[2]), "+f"(c[3])
        : "r"(a[0]), "r"(a[1]), "r"(a[2]), "r"(a[3]), "r"(b[0]), "r"(b[1]));
}

// per-128B-row XOR swizzle: physical 16B-chunk = chunk ^ (row & 7)
__device__ __forceinline__ uint32_t sw_off(int row, int chunk) {
    return (uint32_t)(row * 128 + ((chunk ^ (row & 7)) << 4));
}

// ---------------------------------------------------------------------------
// dtype / binding detection
// ---------------------------------------------------------------------------
__device__ __forceinline__ int looks_se_bytes(const unsigned char* p) {
    int ok = 1;
#pragma unroll 8
    for (int i = 0; i < 64; ++i) {
        unsigned char b = p[i];
        if (!(b == 0x00 || b >= 0xF8)) ok = 0;
    }
    return ok;
}
__device__ __forceinline__ int looks_i32_groups(const unsigned char* p, int groups,
                                                unsigned char lo_min) {
    int ok = 1;
#pragma unroll 4
    for (int j = 0; j < groups; ++j) {
        unsigned char b0 = p[4 * j], b1 = p[4 * j + 1],
                      b2 = p[4 * j + 2], b3 = p[4 * j + 3];
        unsigned char ext = (b0 >= lo_min) ? 0xFF : 0x00;
        int b0ok = (b0 == 0x00) || (b0 == 0x01 && lo_min == 0xFF) || (b0 >= lo_min);
        if (!(b0ok && b1 == ext && b2 == ext && b3 == ext)) ok = 0;
    }
    return ok;
}

// ---------------------------------------------------------------------------
// Launch 1: fused prep + converts (identical to the R10 377.7us version)
// ---------------------------------------------------------------------------
static constexpr int XBLK = M_TOTAL * K_TOTAL / 8192;   // 4096
static constexpr int WBLK = N_TOTAL * K_TOTAL / 4096;   // 1024

__global__ void __launch_bounds__(256)
prep_cvt_kernel(const float* __restrict__ x, const void* __restrict__ wq,
                const void* __restrict__ c0, const void* __restrict__ c1) {
    const int b = blockIdx.x;
    const int tid = threadIdx.x;
    if (b == 0) {
        const int c0_is_se = looks_se_bytes((const unsigned char*)c0);
        const void*  sep = c0_is_se ? c0 : c1;
        const float* bi  = (const float*)(c0_is_se ? c1 : c0);
        const int se32 = looks_i32_groups((const unsigned char*)sep, 64, 0xF8);
#pragma unroll
        for (int t = 0; t < 8; ++t) {
            const int i = tid + t * 256;
            const int e = se32 ? ((const int*)sep)[i]
                               : (int)((const signed char*)sep)[i];
            g_scale[i] = __int_as_float((127 + e) << 23);   // exact 2^s_exp
            g_bias[i]  = bi[i];
        }
    } else if (b <= XBLK) {
        const size_t slot0 = (size_t)(b - 1) * 2048;
        const float4* xi = reinterpret_cast<const float4*>(x) + slot0;
        uint2*        xo = reinterpret_cast<uint2*>(g_x16) + slot0;
#pragma unroll
        for (int batch = 0; batch < 2; ++batch) {
            float4 v[4];
#pragma unroll
            for (int t = 0; t < 4; ++t)
                v[t] = __ldcs(xi + tid + (batch * 4 + t) * 256);
#pragma unroll
            for (int t = 0; t < 4; ++t) {
                __half2 a = __floats2half2_rn(v[t].x, v[t].y);
                __half2 c = __floats2half2_rn(v[t].z, v[t].w);
                uint2 o;
                o.x = *reinterpret_cast<const uint32_t*>(&a);
                o.y = *reinterpret_cast<const uint32_t*>(&c);
                xo[tid + (batch * 4 + t) * 256] = o;
            }
        }
    } else {
        const int w_is32 = looks_i32_groups((const unsigned char*)wq, 64, 0xFF);
        const size_t e0 = (size_t)(b - 1 - XBLK) * 4096;
        if (w_is32) {
            const int4* wi = reinterpret_cast<const int4*>((const int*)wq + e0);
            int4 v[4];
#pragma unroll
            for (int t = 0; t < 4; ++t)
                v[t] = __ldcs(wi + tid + t * 256);
#pragma unroll
            for (int t = 0; t < 4; ++t) {
                const int slot = tid + t * 256;
                uint32_t u0 = (((uint32_t)v[t].x >> 16) & 0x8000u)
                            | ((uint32_t)(v[t].x & 1) * 0x3C00u);
                uint32_t u1 = (((uint32_t)v[t].y >> 16) & 0x8000u)
                            | ((uint32_t)(v[t].y & 1) * 0x3C00u);
                uint32_t u2 = (((uint32_t)v[t].z >> 16) & 0x8000u)
                            | ((uint32_t)(v[t].z & 1) * 0x3C00u);
                uint32_t u3 = (((uint32_t)v[t].w >> 16) & 0x8000u)
                            | ((uint32_t)(v[t].w & 1) * 0x3C00u);
                uint2 o; o.x = u0 | (u1 << 16); o.y = u2 | (u3 << 16);
                reinterpret_cast<uint2*>(g_w16 + e0)[slot] = o;
            }
        } else {
#pragma unroll
            for (int t = 0; t < 2; ++t) {
                const int slot = tid + t * 256;
                unsigned long long v = reinterpret_cast<const unsigned long long*>(
                    (const signed char*)wq + e0)[slot];
                uint32_t h2[4];
#pragma unroll
                for (int j = 0; j < 4; ++j) {
                    int b0 = (int)(signed char)(v >> (16 * j));
                    int b1 = (int)(signed char)(v >> (16 * j + 8));
                    uint32_t u0 = ((uint32_t)(b0 << 8) & 0x8000u) | ((uint32_t)(b0 & 1) * 0x3C00u);
                    uint32_t u1 = ((uint32_t)(b1 << 8) & 0x8000u) | ((uint32_t)(b1 & 1) * 0x3C00u);
                    h2[j] = u0 | (u1 << 16);
                }
                uint4 q; q.x = h2[0]; q.y = h2[1]; q.z = h2[2]; q.w = h2[3];
                reinterpret_cast<uint4*>(g_w16 + e0)[slot] = q;
            }
        }
    }
}

// ---------------------------------------------------------------------------
// Launch 2: GEMM. grid = (8, 128), 512 threads, warp (4m x 4n), tile 32x64.
// 4 stages, 2 chunks per sync round:
//   round r (chunks c=2r, c+1): wait all pending (chunks c, c+1 landed),
//   one bar, issue chunks c+2, c+3 into the stages consumed last round,
//   then 8 ks-steps of MMAs over the two resident stages.
// ---------------------------------------------------------------------------
__global__ void __launch_bounds__(THREADS, 1)
bitlinear_gemm_kernel(float* __restrict__ out) {
    extern __shared__ __align__(1024) char smem[];
    const uint32_t smem_base = smem_to_u32(smem);

    const int tid  = threadIdx.x;
    const int warp = tid >> 5;
    const int lane = tid & 31;
    const int wm   = warp >> 2;      // 0..3
    const int wn   = warp & 3;       // 0..3

    const int n0 = blockIdx.x * BN;
    const int m0 = blockIdx.y * BM;

    const __half* gA = g_x16 + (size_t)m0 * K_TOTAL;
    const __half* gW = g_w16 + (size_t)n0 * K_TOTAL;

    auto issue_stage = [&](int c) {
        const uint32_t sa = smem_base + (uint32_t)(c & 3) * STAGE_BYTES;
        const uint32_t sb = sa + A_STAGE_BYTES;
        const int kb = c * BK;
#pragma unroll
        for (int t = 0; t < 2; ++t) {                 // A: 1024 chunks
            int idx = tid + t * THREADS;
            int r = idx >> 3, ch = idx & 7;
            cp_async_16(sa + sw_off(r, ch), gA + (size_t)r * K_TOTAL + kb + ch * 8);
        }
#pragma unroll
        for (int t = 0; t < 4; ++t) {                 // B: 2048 chunks
            int idx = tid + t * THREADS;
            int r = idx >> 3, ch = idx & 7;
            cp_async_16(sb + sw_off(r, ch), gW + (size_t)r * K_TOTAL + kb + ch * 8);
        }
    };

    // prologue: chunks 0,1 in one commit group
    issue_stage(0); issue_stage(1); cp_async_commit();

    float acc[2][8][4];
#pragma unroll
    for (int i = 0; i < 2; ++i)
#pragma unroll
        for (int j = 0; j < 8; ++j)
#pragma unroll
            for (int k = 0; k < 4; ++k) acc[i][j][k] = 0.f;

    const int a_row_in = (lane & 7) + ((lane >> 3) & 1) * 8;
    const int a_chpar  = lane >> 4;
    const int b_row_in = ((lane >> 4) << 3) + (lane & 7);
    const int b_chpar  = (lane >> 3) & 1;

    // single-buffered per-ks compute on one stage (R10-proven body)
    auto compute_stage = [&](uint32_t sa, uint32_t sb) {
#pragma unroll
        for (int ks = 0; ks < 4; ++ks) {
            uint32_t af[2][4];
#pragma unroll
            for (int i = 0; i < 2; ++i) {
                int m = wm * 32 + i * 16 + a_row_in;
                ldsm_x4(af[i][0], af[i][1], af[i][2], af[i][3],
                        sa + sw_off(m, ks * 2 + a_chpar));
            }
            uint32_t bf[8][2];
#pragma unroll
            for (int p = 0; p < 4; ++p) {
                int n = wn * 64 + p * 16 + b_row_in;
                uint32_t r0, r1, r2, r3;
                ldsm_x4(r0, r1, r2, r3, sb + sw_off(n, ks * 2 + b_chpar));
                bf[2 * p][0] = r0;     bf[2 * p][1] = r1;
                bf[2 * p + 1][0] = r2; bf[2 * p + 1][1] = r3;
            }
#pragma unroll
            for (int i = 0; i < 2; ++i)
#pragma unroll
                for (int j = 0; j < 8; ++j)
                    mma_16816(acc[i][j], af[i], bf[j]);
        }
    };

#pragma unroll 1
    for (int c = 0; c < KITERS; c += 2) {
        cp_async_wait<0>();              // chunks c, c+1 resident
        __syncthreads();                 // all warps done reading the 2 stages
                                         // we are about to overwrite
        if (c + 2 < KITERS) {
            issue_stage(c + 2);
            issue_stage(c + 3);
            cp_async_commit();
        }
        const uint32_t sa0 = smem_base + (uint32_t)(c & 3) * STAGE_BYTES;
        const uint32_t sa1 = smem_base + (uint32_t)((c + 1) & 3) * STAGE_BYTES;
        compute_stage(sa0, sa0 + A_STAGE_BYTES);
        compute_stage(sa1, sa1 + A_STAGE_BYTES);
    }

    // epilogue: y * 2^s_exp + bias; streaming stores
    const int col_lo = 2 * (lane & 3);
    const int row_lo = lane >> 2;
#pragma unroll
    for (int j = 0; j < 8; ++j) {
        const int nc = n0 + wn * 64 + j * 8 + col_lo;
        const float s0 = g_scale[nc], s1 = g_scale[nc + 1];
        const float b0 = g_bias[nc],  b1 = g_bias[nc + 1];
#pragma unroll
        for (int i = 0; i < 2; ++i) {
            const int mr = m0 + wm * 32 + i * 16 + row_lo;
            float2 v0, v1;
            v0.x = acc[i][j][0] * s0 + b0;  v0.y = acc[i][j][1] * s1 + b1;
            v1.x = acc[i][j][2] * s0 + b0;  v1.y = acc[i][j][3] * s1 + b1;
            __stcs(reinterpret_cast<float2*>(out + (size_t)mr * N_TOTAL + nc), v0);
            __stcs(reinterpret_cast<float2*>(out + (size_t)(mr + 8) * N_TOTAL + nc), v1);
        }
    }
}

// ---------------------------------------------------------------------------
// host launcher — bind by element count; 2 launches per call
// ---------------------------------------------------------------------------
extern "C" void kernel_launch(void* const* d_in, const int* in_sizes, int n_in,
                              void* d_out, int out_size) {
    const void* x_p  = nullptr;
    const void* w_p  = nullptr;
    const void* c0_p = nullptr;
    const void* c1_p = nullptr;
    for (int i = 0; i < n_in; ++i) {
        if      (in_sizes[i] == M_TOTAL * K_TOTAL) x_p = d_in[i];
        else if (in_sizes[i] == N_TOTAL * K_TOTAL) w_p = d_in[i];
        else if (!c0_p)                            c0_p = d_in[i];
        else                                       c1_p = d_in[i];
    }
    float* out = (float*)d_out;

    static bool attr_set = false;
    if (!attr_set) {
        cudaFuncSetAttribute(bitlinear_gemm_kernel,
                             cudaFuncAttributeMaxDynamicSharedMemorySize, SMEM_TOTAL);
        attr_set = true;
    }

    prep_cvt_kernel<<<1 + XBLK + WBLK, 256>>>((const float*)x_p, w_p, c0_p, c1_p);

    dim3 grid(N_TOTAL / BN, M_TOTAL / BM);   // (8, 128), n fastest
    bitlinear_gemm_kernel<<<grid, THREADS, SMEM_TOTAL>>>(out);
}